// round 7
// baseline (speedup 1.0000x reference)
#include <cuda_runtime.h>

#define B_   4
#define C_   256
#define CR_  64
#define H_   64
#define W_   64
#define HW_  4096
#define KK_  49
#define G_   16
#define GC_  16
#define OT_  784    // K*K*GROUPS

typedef unsigned long long u64;

// scratch
__device__ float g_x[B_ * CR_ * HW_];          // 4 MB
__device__ float g_w[B_ * OT_ * HW_];          // 51.4 MB dynamic weights

// ---------------- packed f32x2 helpers ----------------
__device__ __forceinline__ u64 pk2(float lo, float hi) {
    u64 r; asm("mov.b64 %0, {%1,%2};" : "=l"(r) : "f"(lo), "f"(hi)); return r;
}
__device__ __forceinline__ void upk2(u64 v, float& lo, float& hi) {
    asm("mov.b64 {%0,%1}, %2;" : "=f"(lo), "=f"(hi) : "l"(v));
}
__device__ __forceinline__ void fma2(u64& d, u64 a, u64 b) {
    asm("fma.rn.f32x2 %0, %1, %2, %0;" : "+l"(d) : "l"(a), "l"(b));
}

// ---------------------------------------------------------------------------
// Kernel 1: x = relu(bn(w1 @ guide)).
// 64-px tiles, grid (64, B) = 256 blocks, 256 thr (8 warps: 32 px-pair lanes
// x 8 r-groups of 8 r). Register-prefetch of next c-chunk overlaps LDG.
// ---------------------------------------------------------------------------
__global__ __launch_bounds__(256) void k1_compute_x(
    const float* __restrict__ guide,
    const float* __restrict__ w1,
    const float* __restrict__ gamma,
    const float* __restrict__ beta,
    const float* __restrict__ mean,
    const float* __restrict__ var)
{
    __shared__ float inv_s[CR_];
    __shared__ float bias_s[CR_];
    __shared__ float gtile[16][64];      // [c_chunk][px]
    __shared__ u64   w1t2[16 * CR_];     // [c_chunk][r], BN-folded dup pairs

    const int t    = threadIdx.x;
    const int b    = blockIdx.y;
    const int pix0 = blockIdx.x * 64;

    if (t < CR_) {
        float iv  = gamma[t] * rsqrtf(var[t] + 1e-5f);
        inv_s[t]  = iv;
        bias_s[t] = beta[t] - mean[t] * iv;
    }
    __syncthreads();

    const int L  = t & 31;       // px pair {2L, 2L+1}
    const int rg = t >> 5;       // 8 r values: rg*8 .. rg*8+7

    // loader roles
    const int lcc = t >> 4, lp4 = t & 15;   // guide: [cc][p4*4..+3]
    const int wcc = t & 15,  wr0 = t >> 4;  // w1: cc, r = wr0 + 16j

    u64 acc[8];
    #pragma unroll
    for (int j = 0; j < 8; j++) acc[j] = 0ull;

    // ---- load chunk 0 ----
    float4 gv = *(const float4*)&guide[(b * C_ + lcc) * HW_ + pix0 + lp4 * 4];
    float wv[4];
    #pragma unroll
    for (int j = 0; j < 4; j++)
        wv[j] = w1[(wr0 + 16 * j) * C_ + wcc];

    *(float4*)&gtile[lcc][lp4 * 4] = gv;
    #pragma unroll
    for (int j = 0; j < 4; j++) {
        int r = wr0 + 16 * j;
        float s = wv[j] * inv_s[r];
        w1t2[wcc * CR_ + r] = pk2(s, s);
    }
    __syncthreads();

    for (int c0 = 16; c0 <= C_; c0 += 16) {
        const bool more = (c0 < C_);
        if (more) {                       // prefetch next chunk into regs
            gv = *(const float4*)&guide[(b * C_ + c0 + lcc) * HW_ + pix0 + lp4 * 4];
            #pragma unroll
            for (int j = 0; j < 4; j++)
                wv[j] = w1[(wr0 + 16 * j) * C_ + c0 + wcc];
        }

        // compute current chunk from smem
        #pragma unroll 4
        for (int cc = 0; cc < 16; cc++) {
            u64 g0 = *(const u64*)&gtile[cc][2 * L];
            ulonglong2 wab = *(const ulonglong2*)&w1t2[cc * CR_ + rg * 8];
            ulonglong2 wcd = *(const ulonglong2*)&w1t2[cc * CR_ + rg * 8 + 2];
            ulonglong2 wef = *(const ulonglong2*)&w1t2[cc * CR_ + rg * 8 + 4];
            ulonglong2 wgh = *(const ulonglong2*)&w1t2[cc * CR_ + rg * 8 + 6];
            fma2(acc[0], wab.x, g0); fma2(acc[1], wab.y, g0);
            fma2(acc[2], wcd.x, g0); fma2(acc[3], wcd.y, g0);
            fma2(acc[4], wef.x, g0); fma2(acc[5], wef.y, g0);
            fma2(acc[6], wgh.x, g0); fma2(acc[7], wgh.y, g0);
        }
        __syncthreads();

        if (more) {
            *(float4*)&gtile[lcc][lp4 * 4] = gv;
            #pragma unroll
            for (int j = 0; j < 4; j++) {
                int r = wr0 + 16 * j;
                float s = wv[j] * inv_s[r];
                w1t2[wcc * CR_ + r] = pk2(s, s);
            }
        }
        __syncthreads();
    }

    #pragma unroll
    for (int rr = 0; rr < 8; rr++) {
        int r = rg * 8 + rr;
        float bb = bias_s[r];
        float a, c;
        upk2(acc[rr], a, c);
        *(float2*)&g_x[(b * CR_ + r) * HW_ + pix0 + 2 * L] =
            make_float2(fmaxf(a + bb, 0.f), fmaxf(c + bb, 0.f));
    }
}

// ---------------------------------------------------------------------------
// Kernel 2': weight GEMM  g_w[b][o][px] = w2[o,:] . x[b,:,px] + b2[o]
// Tile 112 o x 128 px, K = 64. 256 thr: 16 og(7 o) x 16 pg(8 px).
// 28 u64 accs, ~80 regs, 2 CTAs/SM. FMA-bound (11 crossbar vs 14 fma cyc/r).
// grid (7, 32, B)
// ---------------------------------------------------------------------------
#define WS_U64   (64 * 113)                 // [r][o] dup pairs, pad 113
#define XS_OFF   (WS_U64 * 2)               // float idx of xs[64][128]
#define B2S_OFF  (XS_OFF + 64 * 128)
#define SMEMW_FLOATS (B2S_OFF + 112)
#define SMEMW_BYTES  (SMEMW_FLOATS * 4)

__global__ __launch_bounds__(256) void k2_wgemm(
    const float* __restrict__ w2,
    const float* __restrict__ b2)
{
    extern __shared__ float smw[];
    u64*   ws  = (u64*)smw;
    float* xs  = smw + XS_OFF;
    float* b2s = smw + B2S_OFF;

    const int t   = threadIdx.x;
    const int o0  = blockIdx.x * 112;
    const int px0 = blockIdx.y * 128;
    const int b   = blockIdx.z;

    // x tile [64 r][128 px] via float4
    {
        const float4* src = (const float4*)&g_x[b * CR_ * HW_ + px0];
        #pragma unroll
        for (int j = 0; j < 8; j++) {
            int idx = t + 256 * j;            // 2048 float4
            int r = idx >> 5, c4 = idx & 31;
            *(float4*)&xs[r * 128 + c4 * 4] = src[r * (HW_ / 4) + c4];
        }
    }
    // w2 slice transposed + duplicated: ws[r*113 + o] = {w,w}
    #pragma unroll
    for (int j = 0; j < 28; j++) {
        int idx = t + 256 * j;                 // 7168 = 112*64
        int o = idx >> 6, r = idx & 63;
        float v = w2[(o0 + o) * CR_ + r];      // coalesced over r
        ws[r * 113 + o] = pk2(v, v);
    }
    if (t < 112) b2s[t] = b2[o0 + t];
    __syncthreads();

    const int og = t >> 4;       // 0..15 -> o = og*7 .. +6
    const int pg = t & 15;       // 0..15 -> px = pg*8 .. +7

    u64 acc[7][4];
    #pragma unroll
    for (int i = 0; i < 7; i++)
        #pragma unroll
        for (int j = 0; j < 4; j++) acc[i][j] = 0ull;

    const int ob = og * 7;
    #pragma unroll 4
    for (int r = 0; r < CR_; r++) {
        ulonglong2 xa = *(const ulonglong2*)&xs[r * 128 + pg * 8];
        ulonglong2 xb = *(const ulonglong2*)&xs[r * 128 + pg * 8 + 4];
        const u64* wr = &ws[r * 113 + ob];
        #pragma unroll
        for (int oo = 0; oo < 7; oo++) {
            u64 w = wr[oo];                    // 2-addr LDS.64, 1 phase
            fma2(acc[oo][0], w, xa.x);
            fma2(acc[oo][1], w, xa.y);
            fma2(acc[oo][2], w, xb.x);
            fma2(acc[oo][3], w, xb.y);
        }
    }

    #pragma unroll
    for (int oo = 0; oo < 7; oo++) {
        float bv = b2s[ob + oo];
        float l0, h0, l1, h1, l2, h2, l3, h3;
        upk2(acc[oo][0], l0, h0); upk2(acc[oo][1], l1, h1);
        upk2(acc[oo][2], l2, h2); upk2(acc[oo][3], l3, h3);
        float* dst = &g_w[(b * OT_ + o0 + ob + oo) * HW_ + px0 + pg * 8];
        *(float4*)dst       = make_float4(l0 + bv, h0 + bv, l1 + bv, h1 + bv);
        *(float4*)(dst + 4) = make_float4(l2 + bv, h2 + bv, l3 + bv, h3 + bv);
    }
}

// ---------------------------------------------------------------------------
// Kernel 3: aggregation + residual.  4-row tiles (256 px), 2 groups/block.
// 512 thr: pxq = t&127 (pixel pair), chq = t>>7 (4 channels).
// grid (16, B, 8).  Halo overlap reduced 4x -> 2.5x.
// ---------------------------------------------------------------------------
__global__ __launch_bounds__(512) void k3_aggregate(
    const float* __restrict__ feat,
    float* __restrict__ out)
{
    __shared__ float fh[16 * 10 * 72];       // [c][iy 0..9][72] = 46.1 KB

    const int t   = threadIdx.x;
    const int y0  = blockIdx.x * 4;
    const int b   = blockIdx.y;
    const int gh  = blockIdx.z;              // groups 2*gh, 2*gh+1

    const int pxq = t & 127;                 // pixel pair p = 2*pxq
    const int chq = t >> 7;                  // channels 4*chq .. +3
    const int p   = 2 * pxq;
    const int ry  = p >> 6;                  // 0..3
    const int cx  = p & 63;                  // even

    for (int gi = 0; gi < 2; gi++) {
        const int g = gh * 2 + gi;

        // ---- halo: 16 ch x 10 rows x 70 cols (stride 72), zero-pad ----
        #pragma unroll
        for (int j = 0; j < 22; j++) {
            int idx = t + 512 * j;
            if (idx < 16 * 700) {
                int cc  = idx / 700;
                int rem = idx - cc * 700;
                int iy  = rem / 70;
                int ix  = rem - iy * 70;
                int gy = y0 + iy - 3, gx = ix - 3;
                float v = 0.f;
                if ((unsigned)gy < 64u && (unsigned)gx < 64u)
                    v = feat[(b * C_ + g * GC_ + cc) * HW_ + gy * W_ + gx];
                fh[cc * 720 + iy * 72 + ix] = v;
            }
        }
        __syncthreads();

        float oacc[2][4] = {{0.f,0.f,0.f,0.f},{0.f,0.f,0.f,0.f}};

        const float* wbase =
            &g_w[(b * OT_ + g * KK_) * HW_ + (y0 + ry) * W_ + cx];

        #pragma unroll
        for (int ky = 0; ky < 7; ky++) {
            float wk0[7], wk1[7];
            #pragma unroll
            for (int kx = 0; kx < 7; kx++) {
                u64 wv = *(const u64*)(wbase + (ky * 7 + kx) * HW_);
                upk2(wv, wk0[kx], wk1[kx]);
            }
            #pragma unroll
            for (int c = 0; c < 4; c++) {
                const float* frow =
                    &fh[(chq * 4 + c) * 720 + (ry + ky) * 72 + cx];
                float2 f0 = *(const float2*)(frow);
                float2 f1 = *(const float2*)(frow + 2);
                float2 f2 = *(const float2*)(frow + 4);
                float2 f3 = *(const float2*)(frow + 6);
                float e[8] = {f0.x, f0.y, f1.x, f1.y,
                              f2.x, f2.y, f3.x, f3.y};
                #pragma unroll
                for (int kx = 0; kx < 7; kx++) {
                    oacc[0][c] += wk0[kx] * e[kx];
                    oacc[1][c] += wk1[kx] * e[kx + 1];
                }
            }
        }

        #pragma unroll
        for (int c = 0; c < 4; c++) {
            int cc = chq * 4 + c;
            int ch = g * GC_ + cc;
            float r0 = fh[cc * 720 + (ry + 3) * 72 + cx + 3];
            float r1 = fh[cc * 720 + (ry + 3) * 72 + cx + 4];
            *(float2*)&out[(b * C_ + ch) * HW_ + (y0 + ry) * W_ + cx] =
                make_float2(oacc[0][c] + r0, oacc[1][c] + r1);
        }
        __syncthreads();   // before halo overwrite
    }
}

// ---------------------------------------------------------------------------
extern "C" void kernel_launch(void* const* d_in, const int* in_sizes, int n_in,
                              void* d_out, int out_size)
{
    const float* feat  = (const float*)d_in[0];
    const float* guide = (const float*)d_in[1];
    const float* w1    = (const float*)d_in[2];
    const float* gamma = (const float*)d_in[3];
    const float* beta  = (const float*)d_in[4];
    const float* mean  = (const float*)d_in[5];
    const float* var   = (const float*)d_in[6];
    const float* w2    = (const float*)d_in[7];
    const float* b2    = (const float*)d_in[8];
    float* out = (float*)d_out;

    cudaFuncSetAttribute(k2_wgemm,
                         cudaFuncAttributeMaxDynamicSharedMemorySize,
                         SMEMW_BYTES);

    k1_compute_x<<<dim3(64, B_), 256>>>(guide, w1, gamma, beta, mean, var);
    k2_wgemm<<<dim3(7, 32, B_), 256, SMEMW_BYTES>>>(w2, b2);
    k3_aggregate<<<dim3(16, B_, 8), 512>>>(feat, out);
}

// round 8
// speedup vs baseline: 1.0146x; 1.0146x over previous
#include <cuda_runtime.h>

#define B_   4
#define C_   256
#define CR_  64
#define H_   64
#define W_   64
#define HW_  4096
#define KK_  49
#define G_   16
#define GC_  16
#define OT_  784    // K*K*GROUPS

typedef unsigned long long u64;

// scratch
__device__ float g_x[B_ * CR_ * HW_];          // 4 MB
__device__ float g_w[B_ * OT_ * HW_];          // 51.4 MB dynamic weights

// ---------------- packed f32x2 helpers ----------------
__device__ __forceinline__ u64 pk2(float lo, float hi) {
    u64 r; asm("mov.b64 %0, {%1,%2};" : "=l"(r) : "f"(lo), "f"(hi)); return r;
}
__device__ __forceinline__ void upk2(u64 v, float& lo, float& hi) {
    asm("mov.b64 {%0,%1}, %2;" : "=f"(lo), "=f"(hi) : "l"(v));
}
__device__ __forceinline__ void fma2(u64& d, u64 a, u64 b) {
    asm("fma.rn.f32x2 %0, %1, %2, %0;" : "+l"(d) : "l"(a), "l"(b));
}

// ---------------------------------------------------------------------------
// Kernel 1: x = relu(bn(w1 @ guide)).
// Block = one image row (64 px). 256 thr = 32 px-pair lanes x 8 r-groups.
// guide streamed by LDG.64 in the main loop (no guide smem, no load syncs) ->
// continuous independent loads, high MLP. w1 staged in 128-c smem chunks.
// grid (64, B). ~68 KB smem -> 3 CTAs/SM.
// ---------------------------------------------------------------------------
__global__ __launch_bounds__(256) void k1_compute_x(
    const float* __restrict__ guide,
    const float* __restrict__ w1,
    const float* __restrict__ gamma,
    const float* __restrict__ beta,
    const float* __restrict__ mean,
    const float* __restrict__ var)
{
    __shared__ float inv_s[CR_];
    __shared__ float bias_s[CR_];
    __shared__ u64   w1d[128 * 66];      // [cc][r] dup pairs, pad 66 (16B align)

    const int t = threadIdx.x;
    const int y = blockIdx.x;
    const int b = blockIdx.y;

    if (t < CR_) {
        float iv  = gamma[t] * rsqrtf(var[t] + 1e-5f);
        inv_s[t]  = iv;
        bias_s[t] = beta[t] - mean[t] * iv;
    }
    __syncthreads();

    const int lane = t & 31;     // px pair {2*lane, 2*lane+1}
    const int rg   = t >> 5;     // 8 r values: rg*8 .. rg*8+7

    u64 acc[8];
    #pragma unroll
    for (int j = 0; j < 8; j++) acc[j] = 0ull;

    const float* grow = &guide[(size_t)b * C_ * HW_ + y * W_ + 2 * lane];

    for (int c0 = 0; c0 < C_; c0 += 128) {
        // stage 128-c w1 chunk (BN-folded, duplicated pairs, transposed)
        #pragma unroll
        for (int j = 0; j < 32; j++) {
            int idx = t + 256 * j;           // 8192 = 128 cc x 64 r
            int cc = idx & 127, r = idx >> 7;
            float v = w1[r * C_ + c0 + cc] * inv_s[r];
            w1d[cc * 66 + r] = pk2(v, v);
        }
        __syncthreads();

        #pragma unroll 4
        for (int c = 0; c < 128; c++) {
            u64 gv = *(const u64*)&grow[(size_t)(c0 + c) * HW_];
            const u64* wp = &w1d[c * 66 + rg * 8];
            ulonglong2 w01 = *(const ulonglong2*)&wp[0];   // warp-broadcast
            ulonglong2 w23 = *(const ulonglong2*)&wp[2];
            ulonglong2 w45 = *(const ulonglong2*)&wp[4];
            ulonglong2 w67 = *(const ulonglong2*)&wp[6];
            fma2(acc[0], w01.x, gv); fma2(acc[1], w01.y, gv);
            fma2(acc[2], w23.x, gv); fma2(acc[3], w23.y, gv);
            fma2(acc[4], w45.x, gv); fma2(acc[5], w45.y, gv);
            fma2(acc[6], w67.x, gv); fma2(acc[7], w67.y, gv);
        }
        __syncthreads();
    }

    #pragma unroll
    for (int rr = 0; rr < 8; rr++) {
        int r = rg * 8 + rr;
        float bb = bias_s[r];
        float a, c;
        upk2(acc[rr], a, c);
        *(float2*)&g_x[((size_t)b * CR_ + r) * HW_ + y * W_ + 2 * lane] =
            make_float2(fmaxf(a + bb, 0.f), fmaxf(c + bb, 0.f));
    }
}

// ---------------------------------------------------------------------------
// Kernel 2': weight GEMM  g_w[b][o][px] = w2[o,:] . x[b,:,px] + b2[o]
// Tile 112 o x 128 px, K = 64. 256 thr: 16 og(7 o) x 16 pg(8 px).
// grid (7, 32, B)
// ---------------------------------------------------------------------------
#define WS_U64   (64 * 113)                 // [r][o] dup pairs, pad 113
#define XS_OFF   (WS_U64 * 2)               // float idx of xs[64][128]
#define B2S_OFF  (XS_OFF + 64 * 128)
#define SMEMW_FLOATS (B2S_OFF + 112)
#define SMEMW_BYTES  (SMEMW_FLOATS * 4)

__global__ __launch_bounds__(256) void k2_wgemm(
    const float* __restrict__ w2,
    const float* __restrict__ b2)
{
    extern __shared__ float smw[];
    u64*   ws  = (u64*)smw;
    float* xs  = smw + XS_OFF;
    float* b2s = smw + B2S_OFF;

    const int t   = threadIdx.x;
    const int o0  = blockIdx.x * 112;
    const int px0 = blockIdx.y * 128;
    const int b   = blockIdx.z;

    {
        const float4* src = (const float4*)&g_x[(size_t)b * CR_ * HW_ + px0];
        #pragma unroll
        for (int j = 0; j < 8; j++) {
            int idx = t + 256 * j;            // 2048 float4
            int r = idx >> 5, c4 = idx & 31;
            *(float4*)&xs[r * 128 + c4 * 4] = src[r * (HW_ / 4) + c4];
        }
    }
    #pragma unroll
    for (int j = 0; j < 28; j++) {
        int idx = t + 256 * j;                 // 7168 = 112*64
        int o = idx >> 6, r = idx & 63;
        float v = w2[(o0 + o) * CR_ + r];      // coalesced over r
        ws[r * 113 + o] = pk2(v, v);
    }
    if (t < 112) b2s[t] = b2[o0 + t];
    __syncthreads();

    const int og = t >> 4;       // 0..15 -> o = og*7 .. +6
    const int pg = t & 15;       // 0..15 -> px = pg*8 .. +7

    u64 acc[7][4];
    #pragma unroll
    for (int i = 0; i < 7; i++)
        #pragma unroll
        for (int j = 0; j < 4; j++) acc[i][j] = 0ull;

    const int ob = og * 7;
    #pragma unroll 4
    for (int r = 0; r < CR_; r++) {
        ulonglong2 xa = *(const ulonglong2*)&xs[r * 128 + pg * 8];
        ulonglong2 xb = *(const ulonglong2*)&xs[r * 128 + pg * 8 + 4];
        const u64* wr = &ws[r * 113 + ob];
        #pragma unroll
        for (int oo = 0; oo < 7; oo++) {
            u64 w = wr[oo];
            fma2(acc[oo][0], w, xa.x);
            fma2(acc[oo][1], w, xa.y);
            fma2(acc[oo][2], w, xb.x);
            fma2(acc[oo][3], w, xb.y);
        }
    }

    #pragma unroll
    for (int oo = 0; oo < 7; oo++) {
        float bv = b2s[ob + oo];
        float l0, h0, l1, h1, l2, h2, l3, h3;
        upk2(acc[oo][0], l0, h0); upk2(acc[oo][1], l1, h1);
        upk2(acc[oo][2], l2, h2); upk2(acc[oo][3], l3, h3);
        float* dst = &g_w[((size_t)b * OT_ + o0 + ob + oo) * HW_ + px0 + pg * 8];
        *(float4*)dst       = make_float4(l0 + bv, h0 + bv, l1 + bv, h1 + bv);
        *(float4*)(dst + 4) = make_float4(l2 + bv, h2 + bv, l3 + bv, h3 + bv);
    }
}

// ---------------------------------------------------------------------------
// Kernel 3: aggregation + residual.  8-row strip x 1 group per block.
// grid (8, B, 16), 512 thr, 64.5 KB halo -> 3 CTAs/SM (48 warps: hides the
// 51 MB g_w DRAM stream).  Halo loader: warp-row mapping, no divisions.
// ---------------------------------------------------------------------------
__global__ __launch_bounds__(512) void k3_aggregate(
    const float* __restrict__ feat,
    float* __restrict__ out)
{
    __shared__ float fh[16 * 14 * 72];       // [c][iy 0..13][72] = 64.5 KB

    const int t  = threadIdx.x;
    const int y0 = blockIdx.x * 8;
    const int b  = blockIdx.y;
    const int g  = blockIdx.z;

    // ---- halo: 16 ch x 14 rows x 70 cols. warp w owns rows w*14 .. w*14+13
    {
        const int w = t >> 5, lane = t & 31;
        #pragma unroll
        for (int rr = 0; rr < 14; rr++) {
            int rowid = w * 14 + rr;          // 0..223 = iy*16 + c
            int c  = rowid & 15;
            int iy = rowid >> 4;
            int gy = y0 + iy - 3;
            const float* src =
                &feat[((size_t)b * C_ + g * GC_ + c) * HW_ + gy * W_];
            float* dst = &fh[c * 1008 + iy * 72];
            #pragma unroll
            for (int s = 0; s < 3; s++) {
                int ix = lane + 32 * s;
                if (ix < 70) {
                    int gx = ix - 3;
                    float v = 0.f;
                    if ((unsigned)gy < 64u && (unsigned)gx < 64u)
                        v = src[gx];
                    dst[ix] = v;
                }
            }
        }
    }
    __syncthreads();

    const int pxq = t & 127;                 // pixel pair within 4-row slab
    const int chq = t >> 7;                  // channels 4*chq .. +3
    const int p   = 2 * pxq;
    const int ry4 = p >> 6;                  // row within slab (0..3)
    const int cx  = p & 63;                  // even column

    #pragma unroll
    for (int rb = 0; rb < 2; rb++) {
        const int ry = rb * 4 + ry4;         // 0..7

        float oacc[2][4] = {{0.f,0.f,0.f,0.f},{0.f,0.f,0.f,0.f}};

        const float* wbase =
            &g_w[((size_t)b * OT_ + g * KK_) * HW_ + (y0 + ry) * W_ + cx];

        #pragma unroll
        for (int ky = 0; ky < 7; ky++) {
            float wk0[7], wk1[7];
            #pragma unroll
            for (int kx = 0; kx < 7; kx++) {
                u64 wv = *(const u64*)(wbase + (size_t)(ky * 7 + kx) * HW_);
                upk2(wv, wk0[kx], wk1[kx]);
            }
            #pragma unroll
            for (int c = 0; c < 4; c++) {
                const float* frow =
                    &fh[(chq * 4 + c) * 1008 + (ry + ky) * 72 + cx];
                float2 f0 = *(const float2*)(frow);
                float2 f1 = *(const float2*)(frow + 2);
                float2 f2 = *(const float2*)(frow + 4);
                float2 f3 = *(const float2*)(frow + 6);
                float e[8] = {f0.x, f0.y, f1.x, f1.y,
                              f2.x, f2.y, f3.x, f3.y};
                #pragma unroll
                for (int kx = 0; kx < 7; kx++) {
                    oacc[0][c] += wk0[kx] * e[kx];
                    oacc[1][c] += wk1[kx] * e[kx + 1];
                }
            }
        }

        #pragma unroll
        for (int c = 0; c < 4; c++) {
            int cc = chq * 4 + c;
            int ch = g * GC_ + cc;
            float r0 = fh[cc * 1008 + (ry + 3) * 72 + cx + 3];
            float r1 = fh[cc * 1008 + (ry + 3) * 72 + cx + 4];
            *(float2*)&out[((size_t)b * C_ + ch) * HW_ + (y0 + ry) * W_ + cx] =
                make_float2(oacc[0][c] + r0, oacc[1][c] + r1);
        }
    }
}

// ---------------------------------------------------------------------------
extern "C" void kernel_launch(void* const* d_in, const int* in_sizes, int n_in,
                              void* d_out, int out_size)
{
    const float* feat  = (const float*)d_in[0];
    const float* guide = (const float*)d_in[1];
    const float* w1    = (const float*)d_in[2];
    const float* gamma = (const float*)d_in[3];
    const float* beta  = (const float*)d_in[4];
    const float* mean  = (const float*)d_in[5];
    const float* var   = (const float*)d_in[6];
    const float* w2    = (const float*)d_in[7];
    const float* b2    = (const float*)d_in[8];
    float* out = (float*)d_out;

    cudaFuncSetAttribute(k2_wgemm,
                         cudaFuncAttributeMaxDynamicSharedMemorySize,
                         SMEMW_BYTES);

    k1_compute_x<<<dim3(64, B_), 256>>>(guide, w1, gamma, beta, mean, var);
    k2_wgemm<<<dim3(7, 32, B_), 256, SMEMW_BYTES>>>(w2, b2);
    k3_aggregate<<<dim3(8, B_, G_), 512>>>(feat, out);
}

// round 9
// speedup vs baseline: 1.3125x; 1.2936x over previous
#include <cuda_runtime.h>
#include <cstdint>

#define B_   4
#define C_   256
#define CR_  64
#define H_   64
#define W_   64
#define HW_  4096
#define KK_  49
#define G_   16
#define GC_  16
#define OT_  784

typedef unsigned long long u64;

// scratch
__device__ u64   g_w1d[C_ * CR_];          // [c][r] BN-folded dup pairs, 128KB
__device__ u64   g_w2d[7 * CR_ * 128];     // [oc][r][og*8+i] dup pairs, 448KB
__device__ float g_w[B_ * OT_ * HW_];      // 51.4 MB dynamic weights

// ---------------- packed f32x2 helpers ----------------
__device__ __forceinline__ u64 pk2(float lo, float hi) {
    u64 r; asm("mov.b64 %0, {%1,%2};" : "=l"(r) : "f"(lo), "f"(hi)); return r;
}
__device__ __forceinline__ void upk2(u64 v, float& lo, float& hi) {
    asm("mov.b64 {%0,%1}, %2;" : "=f"(lo), "=f"(hi) : "l"(v));
}
__device__ __forceinline__ void fma2(u64& d, u64 a, u64 b) {
    asm("fma.rn.f32x2 %0, %1, %2, %0;" : "+l"(d) : "l"(a), "l"(b));
}
__device__ __forceinline__ void cp16(void* dst_smem, const void* src) {
    unsigned sa = (unsigned)__cvta_generic_to_shared(dst_smem);
    asm volatile("cp.async.cg.shared.global [%0], [%1], 16;" :: "r"(sa), "l"(src));
}
#define CP_COMMIT() asm volatile("cp.async.commit_group;")
#define CP_WAIT1()  asm volatile("cp.async.wait_group 1;")
#define CP_WAIT0()  asm volatile("cp.async.wait_group 0;")

// ---------------------------------------------------------------------------
// k0: one-time weight re-layouts (BN fold + f32x2 duplication)
// grid 260 x 256
// ---------------------------------------------------------------------------
__global__ __launch_bounds__(256) void k0_prep(
    const float* __restrict__ w1,
    const float* __restrict__ gamma,
    const float* __restrict__ beta,   // unused here (bias applied in k12)
    const float* __restrict__ mean,
    const float* __restrict__ var,
    const float* __restrict__ w2)
{
    int idx = blockIdx.x * 256 + threadIdx.x;
    if (idx < C_ * CR_) {
        // w1d: idx = r*256 + c  (coalesced w1 read), dst [c][r]
        int r = idx >> 8, c = idx & 255;
        float iv = gamma[r] * rsqrtf(var[r] + 1e-5f);
        float v = w1[r * C_ + c] * iv;
        g_w1d[c * CR_ + r] = pk2(v, v);
    } else if (idx < C_ * CR_ + OT_ * CR_) {
        int j = idx - C_ * CR_;          // j = p*64 + r, p = o row 0..783
        int p = j >> 6, r = j & 63;
        int oc = p / 112, q = p - oc * 112;
        int og = q / 7,  i = q - og * 7;
        float v = w2[p * CR_ + r];       // coalesced over r
        g_w2d[(oc * CR_ + r) * 128 + og * 8 + i] = pk2(v, v);
    }
}

// ---------------------------------------------------------------------------
// k12: fused  x = relu(bn(w1@guide))  then  g_w = w2@x + b2.
// Block = one image row (64 px). 256 thr. grid (64, B).
// Phase A: 3-slot cp.async ring over (guide 8KB + w1d 16KB) chunks of 32 c.
// Phase B: 7 o-chunks of 112; ws cp.async'd per chunk; tile 7o x 4px.
// dynamic smem = 16384 (xs) + 3*24576 (ring) = 90112 B -> 2 CTAs/SM.
// ---------------------------------------------------------------------------
#define SLOT_BYTES 24576
#define RING_OFF   16384
#define SMEMF_BYTES (RING_OFF + 3 * SLOT_BYTES)

__global__ __launch_bounds__(256) void k12_fused(
    const float* __restrict__ guide,
    const float* __restrict__ gamma,
    const float* __restrict__ beta,
    const float* __restrict__ mean,
    const float* __restrict__ var,
    const float* __restrict__ b2)
{
    extern __shared__ char sm[];
    float* xs  = (float*)sm;                       // [64r][64px]
    char*  ring = sm + RING_OFF;                   // 3 x (guide 8KB | w1d 16KB)
    u64*   ws  = (u64*)(sm + RING_OFF);            // phase B: [64r][128] 64KB
    float* b2s = (float*)(sm + RING_OFF + 65536);  // phase B: [112]

    __shared__ float bias_s[CR_];

    const int t = threadIdx.x;
    const int y = blockIdx.x;
    const int b = blockIdx.y;

    if (t < CR_) {
        float iv = gamma[t] * rsqrtf(var[t] + 1e-5f);
        bias_s[t] = beta[t] - mean[t] * iv;
    }

    const int pgA = t & 15;      // 4 px: pgA*4 .. +3 (2 pairs)
    const int rgA = t >> 4;      // 4 r:  rgA*4 .. +3

    // ---- cp.async issue of phase-A chunk k into slot k%3 ----
    auto issueA = [&](int k) {
        char* slot = ring + (k % 3) * SLOT_BYTES;
        int c0 = k * 32;
        #pragma unroll
        for (int j = 0; j < 2; j++) {              // guide 32c x 64px
            int idx = t + 256 * j;
            int cc = idx >> 4, p4 = idx & 15;
            cp16(slot + (cc * 64 + p4 * 4) * 4,
                 &guide[((size_t)b * C_ + c0 + cc) * HW_ + y * W_ + p4 * 4]);
        }
        const char* wsrc = (const char*)(g_w1d + (size_t)c0 * CR_);
        #pragma unroll
        for (int j = 0; j < 4; j++) {              // w1d 32c x 64r dup
            int idx = t + 256 * j;
            cp16(slot + 8192 + idx * 16, wsrc + idx * 16);
        }
        CP_COMMIT();
    };

    issueA(0);
    issueA(1);

    u64 accA[4][2];
    #pragma unroll
    for (int i = 0; i < 4; i++) { accA[i][0] = 0ull; accA[i][1] = 0ull; }

    for (int k = 0; k < 8; k++) {
        CP_WAIT1();              // chunk k complete (1 newer group may pend)
        __syncthreads();
        if (k + 2 < 8) issueA(k + 2); else CP_COMMIT();  // uniform group count

        const float* gt  = (const float*)(ring + (k % 3) * SLOT_BYTES);
        const u64*   w1s = (const u64*)(ring + (k % 3) * SLOT_BYTES + 8192);

        #pragma unroll 8
        for (int c = 0; c < 32; c++) {
            ulonglong2 xv  = *(const ulonglong2*)&gt[c * 64 + pgA * 4];
            ulonglong2 wab = *(const ulonglong2*)&w1s[c * CR_ + rgA * 4];
            ulonglong2 wcd = *(const ulonglong2*)&w1s[c * CR_ + rgA * 4 + 2];
            fma2(accA[0][0], wab.x, xv.x); fma2(accA[0][1], wab.x, xv.y);
            fma2(accA[1][0], wab.y, xv.x); fma2(accA[1][1], wab.y, xv.y);
            fma2(accA[2][0], wcd.x, xv.x); fma2(accA[2][1], wcd.x, xv.y);
            fma2(accA[3][0], wcd.y, xv.x); fma2(accA[3][1], wcd.y, xv.y);
        }
        __syncthreads();
    }

    // phase-A epilogue: bias + relu -> xs
    #pragma unroll
    for (int rr = 0; rr < 4; rr++) {
        int r = rgA * 4 + rr;
        float bb = bias_s[r];
        float a0, a1, a2, a3;
        upk2(accA[rr][0], a0, a1);
        upk2(accA[rr][1], a2, a3);
        *(float4*)&xs[r * 64 + pgA * 4] =
            make_float4(fmaxf(a0 + bb, 0.f), fmaxf(a1 + bb, 0.f),
                        fmaxf(a2 + bb, 0.f), fmaxf(a3 + bb, 0.f));
    }
    __syncthreads();

    // ---- phase B: 7 o-chunks of 112 ----
    const int og = t >> 4;       // 16 og x 7 o
    const int pg = t & 15;       // 16 pg x 4 px
    const int ob8 = og * 8;

    for (int oc = 0; oc < 7; oc++) {
        // stage ws: 64KB raw cp.async from g_w2d[oc]
        {
            const char* src = (const char*)(g_w2d + (size_t)oc * CR_ * 128);
            #pragma unroll
            for (int j = 0; j < 16; j++) {
                int idx = t + 256 * j;             // 4096 x 16B
                cp16((char*)ws + idx * 16, src + idx * 16);
            }
        }
        if (t < 112) b2s[t] = b2[oc * 112 + t];
        CP_COMMIT();
        CP_WAIT0();
        __syncthreads();

        u64 acc[7][2];
        #pragma unroll
        for (int i = 0; i < 7; i++) { acc[i][0] = 0ull; acc[i][1] = 0ull; }

        #pragma unroll 4
        for (int r = 0; r < CR_; r++) {
            ulonglong2 xv  = *(const ulonglong2*)&xs[r * 64 + pg * 4];
            const u64* wr  = &ws[r * 128 + ob8];
            ulonglong2 w01 = *(const ulonglong2*)&wr[0];
            ulonglong2 w23 = *(const ulonglong2*)&wr[2];
            ulonglong2 w45 = *(const ulonglong2*)&wr[4];
            u64        w6  = wr[6];
            fma2(acc[0][0], w01.x, xv.x); fma2(acc[0][1], w01.x, xv.y);
            fma2(acc[1][0], w01.y, xv.x); fma2(acc[1][1], w01.y, xv.y);
            fma2(acc[2][0], w23.x, xv.x); fma2(acc[2][1], w23.x, xv.y);
            fma2(acc[3][0], w23.y, xv.x); fma2(acc[3][1], w23.y, xv.y);
            fma2(acc[4][0], w45.x, xv.x); fma2(acc[4][1], w45.x, xv.y);
            fma2(acc[5][0], w45.y, xv.x); fma2(acc[5][1], w45.y, xv.y);
            fma2(acc[6][0], w6,    xv.x); fma2(acc[6][1], w6,    xv.y);
        }

        #pragma unroll
        for (int oo = 0; oo < 7; oo++) {
            int o = oc * 112 + og * 7 + oo;
            float bv = b2s[og * 7 + oo];
            float l0, h0, l1, h1;
            upk2(acc[oo][0], l0, h0);
            upk2(acc[oo][1], l1, h1);
            *(float4*)&g_w[((size_t)b * OT_ + o) * HW_ + y * W_ + pg * 4] =
                make_float4(l0 + bv, h0 + bv, l1 + bv, h1 + bv);
        }
        __syncthreads();   // protect ws before next chunk's cp.async
    }
}

// ---------------------------------------------------------------------------
// k3: aggregation + residual (R8 version). 8-row strip x 1 group per block.
// grid (8, B, 16), 512 thr, 64.5KB halo -> 3 CTAs/SM.
// ---------------------------------------------------------------------------
__global__ __launch_bounds__(512) void k3_aggregate(
    const float* __restrict__ feat,
    float* __restrict__ out)
{
    __shared__ float fh[16 * 14 * 72];

    const int t  = threadIdx.x;
    const int y0 = blockIdx.x * 8;
    const int b  = blockIdx.y;
    const int g  = blockIdx.z;

    {
        const int w = t >> 5, lane = t & 31;
        #pragma unroll
        for (int rr = 0; rr < 14; rr++) {
            int rowid = w * 14 + rr;          // 0..223 = iy*16 + c
            int c  = rowid & 15;
            int iy = rowid >> 4;
            int gy = y0 + iy - 3;
            const float* src =
                &feat[((size_t)b * C_ + g * GC_ + c) * HW_ + gy * W_];
            float* dst = &fh[c * 1008 + iy * 72];
            #pragma unroll
            for (int s = 0; s < 3; s++) {
                int ix = lane + 32 * s;
                if (ix < 70) {
                    int gx = ix - 3;
                    float v = 0.f;
                    if ((unsigned)gy < 64u && (unsigned)gx < 64u)
                        v = src[gx];
                    dst[ix] = v;
                }
            }
        }
    }
    __syncthreads();

    const int pxq = t & 127;
    const int chq = t >> 7;
    const int p   = 2 * pxq;
    const int ry4 = p >> 6;
    const int cx  = p & 63;

    #pragma unroll
    for (int rb = 0; rb < 2; rb++) {
        const int ry = rb * 4 + ry4;

        float oacc[2][4] = {{0.f,0.f,0.f,0.f},{0.f,0.f,0.f,0.f}};

        const float* wbase =
            &g_w[((size_t)b * OT_ + g * KK_) * HW_ + (y0 + ry) * W_ + cx];

        #pragma unroll
        for (int ky = 0; ky < 7; ky++) {
            float wk0[7], wk1[7];
            #pragma unroll
            for (int kx = 0; kx < 7; kx++) {
                u64 wv = *(const u64*)(wbase + (size_t)(ky * 7 + kx) * HW_);
                upk2(wv, wk0[kx], wk1[kx]);
            }
            #pragma unroll
            for (int c = 0; c < 4; c++) {
                const float* frow =
                    &fh[(chq * 4 + c) * 1008 + (ry + ky) * 72 + cx];
                float2 f0 = *(const float2*)(frow);
                float2 f1 = *(const float2*)(frow + 2);
                float2 f2 = *(const float2*)(frow + 4);
                float2 f3 = *(const float2*)(frow + 6);
                float e[8] = {f0.x, f0.y, f1.x, f1.y,
                              f2.x, f2.y, f3.x, f3.y};
                #pragma unroll
                for (int kx = 0; kx < 7; kx++) {
                    oacc[0][c] += wk0[kx] * e[kx];
                    oacc[1][c] += wk1[kx] * e[kx + 1];
                }
            }
        }

        #pragma unroll
        for (int c = 0; c < 4; c++) {
            int cc = chq * 4 + c;
            int ch = g * GC_ + cc;
            float r0 = fh[cc * 1008 + (ry + 3) * 72 + cx + 3];
            float r1 = fh[cc * 1008 + (ry + 3) * 72 + cx + 4];
            *(float2*)&out[((size_t)b * C_ + ch) * HW_ + (y0 + ry) * W_ + cx] =
                make_float2(oacc[0][c] + r0, oacc[1][c] + r1);
        }
    }
}

// ---------------------------------------------------------------------------
extern "C" void kernel_launch(void* const* d_in, const int* in_sizes, int n_in,
                              void* d_out, int out_size)
{
    const float* feat  = (const float*)d_in[0];
    const float* guide = (const float*)d_in[1];
    const float* w1    = (const float*)d_in[2];
    const float* gamma = (const float*)d_in[3];
    const float* beta  = (const float*)d_in[4];
    const float* mean  = (const float*)d_in[5];
    const float* var   = (const float*)d_in[6];
    const float* w2    = (const float*)d_in[7];
    const float* b2    = (const float*)d_in[8];
    float* out = (float*)d_out;

    cudaFuncSetAttribute(k12_fused,
                         cudaFuncAttributeMaxDynamicSharedMemorySize,
                         SMEMF_BYTES);

    k0_prep<<<260, 256>>>(w1, gamma, beta, mean, var, w2);
    k12_fused<<<dim3(64, B_), 256, SMEMF_BYTES>>>(guide, gamma, beta, mean, var, b2);
    k3_aggregate<<<dim3(8, B_, G_), 512>>>(feat, out);
}